// round 14
// baseline (speedup 1.0000x reference)
#include <cuda_runtime.h>
#include <cstdint>

// Row-wise geometry kernel: 6 points (x,y) per row ->
//   out[row][0:15]  = pairwise distances (lexicographic pairs)
//   out[row][15:35] = triplet angles at middle vertex, degrees
//   out[row][35:55] = triangle areas
//
// R14 = R13 + 2 adjacent rows per thread:
//   - 6x LDG.128 per thread (one float4 = two rows' float2 per input array)
//     instead of 12x LDG.64 -> half LSU issue, 2x bytes/request
//   - CTA of 128 threads covers 256 rows; SMEM 56320B dynamic (4 CTAs/SM)
//   - warp flushes one contiguous 14080B slice (64 rows) via TMA bulk store
//   - L2: reads evict_last, writes evict_first; wait_group.READ only

#define NTH   128
#define RPT   2                 // rows per thread
#define ROWS  (NTH * RPT)       // 256 rows per CTA
#define NOUT  55
#define R2D   57.29577951308232f

__device__ __forceinline__ float sqrt_approx(float x) {
    float y;
    asm("sqrt.approx.f32 %0, %1;" : "=f"(y) : "f"(x));
    return y;
}

__device__ __forceinline__ float acos_deg(float x) {
    // Abramowitz & Stegun 4.4.46: acos(x) = sqrt(1-x)*P7(x), |eps| <= 2e-8 rad
    float xa = fabsf(x);
    float p = fmaf(xa, -0.0012624911f, 0.0066700901f);
    p = fmaf(p, xa, -0.0170881256f);
    p = fmaf(p, xa,  0.0308918810f);
    p = fmaf(p, xa, -0.0501743046f);
    p = fmaf(p, xa,  0.0889789874f);
    p = fmaf(p, xa, -0.2145988016f);
    p = fmaf(p, xa,  1.5707963050f);
    float r = sqrt_approx(1.0f - xa) * p * R2D;   // acos(|x|) in degrees
    return (x >= 0.0f) ? r : (180.0f - r);
}

__device__ __forceinline__ float4 ld_pin4(const float4* __restrict__ p, uint64_t pol) {
    float4 v;
    asm volatile("ld.global.nc.L2::cache_hint.v4.f32 {%0,%1,%2,%3}, [%4], %5;"
                 : "=f"(v.x), "=f"(v.y), "=f"(v.z), "=f"(v.w) : "l"(p), "l"(pol));
    return v;
}

extern __shared__ float s[];   // ROWS * NOUT floats = 56320 bytes

__device__ __forceinline__ void compute_row(
    const float px[6], const float py[6], float* __restrict__ srow)
{
    const int PRI[15] = {0,0,0,0,0, 1,1,1,1, 2,2,2, 3,3, 4};
    const int PRJ[15] = {1,2,3,4,5, 2,3,4,5, 3,4,5, 4,5, 5};

    float dxv[15], dyv[15], rsq[15];
    #pragma unroll
    for (int q = 0; q < 15; q++) {
        float ddx = px[PRI[q]] - px[PRJ[q]];
        float ddy = py[PRI[q]] - py[PRJ[q]];
        float sq  = fmaf(ddx, ddx, ddy * ddy);
        float r   = rsqrtf(sq);
        dxv[q] = ddx; dyv[q] = ddy; rsq[q] = r;
        srow[q] = sq * r;                          // distance = sq * rsqrt(sq)
    }

    const int TI[20] = {0,0,0,0,0,0,0,0,0,0, 1,1,1,1,1,1, 2,2,2, 3};
    const int TJ[20] = {1,1,1,1,2,2,2,3,3,4, 2,2,2,3,3,4, 3,3,4, 4};
    const int TK[20] = {2,3,4,5,3,4,5,4,5,5, 3,4,5,4,5,5, 4,5,5, 5};
    const int POFF[5] = {0,5,9,12,14};             // pidx(i,j) = POFF[i]+(j-i-1)

    #pragma unroll
    for (int q = 0; q < 20; q++) {
        const int i = TI[q], j = TJ[q], k = TK[q];
        const int eij = POFF[i] + (j - i - 1);
        const int ejk = POFF[j] + (k - j - 1);
        const int eik = POFF[i] + (k - i - 1);

        // v1 = p_i - p_j = diff_ij ; v2 = p_k - p_j = -diff_jk
        float dot = fmaf(dxv[eij], dxv[ejk], dyv[eij] * dyv[ejk]);
        float c   = -dot * rsq[eij] * rsq[ejk];
        c = fminf(1.0f, fmaxf(-1.0f, c));
        srow[15 + q] = acos_deg(c);

        // shoelace: x_i*dy_jk - x_j*dy_ik + x_k*dy_ij
        float cr = fmaf(px[i], dyv[ejk], fmaf(px[k], dyv[eij], -px[j] * dyv[eik]));
        srow[35 + q] = 0.5f * fabsf(cr);
    }
}

__global__ __launch_bounds__(NTH)
void geom55_kernel(const float4* __restrict__ a0, const float4* __restrict__ a1,
                   const float4* __restrict__ a2, const float4* __restrict__ a3,
                   const float4* __restrict__ a4, const float4* __restrict__ a5,
                   float* __restrict__ out, int n)
{
    const int tid  = threadIdx.x;
    const int wid  = tid >> 5;
    const int lane = tid & 31;

    // Thread t handles global rows r0 = tile*256 + 2t and r0+1.
    const int r0 = blockIdx.x * ROWS + 2 * tid;

    // Uniform prologue
    float* swarp = &s[wid * 64 * NOUT];            // 64 rows = 14080 B slice
    uint32_t saddr;
    asm volatile("{ .reg .u64 t; cvta.to.shared.u64 t, %1; cvt.u32.u64 %0, t; }"
                 : "=r"(saddr) : "l"(swarp));
    uint64_t pol_last, pol_first;
    asm volatile("createpolicy.fractional.L2::evict_last.b64 %0, 1.0;"  : "=l"(pol_last));
    asm volatile("createpolicy.fractional.L2::evict_first.b64 %0, 1.0;" : "=l"(pol_first));

    if (r0 + 1 < n) {
        // One LDG.128 per array = both rows' (x,y)
        const int q4 = r0 >> 1;                    // float4 index
        float4 t0 = ld_pin4(&a0[q4], pol_last);
        float4 t1 = ld_pin4(&a1[q4], pol_last);
        float4 t2 = ld_pin4(&a2[q4], pol_last);
        float4 t3 = ld_pin4(&a3[q4], pol_last);
        float4 t4 = ld_pin4(&a4[q4], pol_last);
        float4 t5 = ld_pin4(&a5[q4], pol_last);

        float pxA[6] = {t0.x, t1.x, t2.x, t3.x, t4.x, t5.x};
        float pyA[6] = {t0.y, t1.y, t2.y, t3.y, t4.y, t5.y};
        float pxB[6] = {t0.z, t1.z, t2.z, t3.z, t4.z, t5.z};
        float pyB[6] = {t0.w, t1.w, t2.w, t3.w, t4.w, t5.w};

        compute_row(pxA, pyA, &s[(2 * tid)     * NOUT]);
        compute_row(pxB, pyB, &s[(2 * tid + 1) * NOUT]);
    } else if (r0 < n) {
        // Single valid row at the very tail
        float px[6], py[6];
        const float2* b0 = (const float2*)a0; const float2* b1 = (const float2*)a1;
        const float2* b2 = (const float2*)a2; const float2* b3 = (const float2*)a3;
        const float2* b4 = (const float2*)a4; const float2* b5 = (const float2*)a5;
        float2 t;
        t = b0[r0]; px[0] = t.x; py[0] = t.y;
        t = b1[r0]; px[1] = t.x; py[1] = t.y;
        t = b2[r0]; px[2] = t.x; py[2] = t.y;
        t = b3[r0]; px[3] = t.x; py[3] = t.y;
        t = b4[r0]; px[4] = t.x; py[4] = t.y;
        t = b5[r0]; px[5] = t.x; py[5] = t.y;
        compute_row(px, py, &s[(2 * tid) * NOUT]);
    }
    __syncwarp();

    // Per-warp flush: warp w's slice = rows [blockIdx.x*256 + w*64, +64)
    const int warpRow0 = blockIdx.x * ROWS + wid * 64;
    const long long gbase = (long long)warpRow0 * NOUT;

    if (warpRow0 + 64 <= n) {
        if (lane == 0) {
            asm volatile("fence.proxy.async.shared::cta;" ::: "memory");
            asm volatile("cp.async.bulk.global.shared::cta.bulk_group.L2::cache_hint"
                         " [%0], [%1], %2, %3;"
                         :: "l"(out + gbase), "r"(saddr), "n"(64 * NOUT * 4), "l"(pol_first)
                         : "memory");
            asm volatile("cp.async.bulk.commit_group;" ::: "memory");
            // READ-wait: SMEM-dealloc safety only; the global drain continues.
            asm volatile("cp.async.bulk.wait_group.read 0;" ::: "memory");
        }
    } else if (warpRow0 < n) {
        // Partial tail slice: scalar flush
        const int tot = (n - warpRow0) * NOUT;
        for (int q = lane; q < tot; q += 32) out[gbase + q] = swarp[q];
    }
}

extern "C" void kernel_launch(void* const* d_in, const int* in_sizes, int n_in,
                              void* d_out, int out_size) {
    const int n = in_sizes[0] / 2;                  // rows (B)
    const int grid = (n + ROWS - 1) / ROWS;
    const int smem = ROWS * NOUT * sizeof(float);   // 56320 B
    cudaFuncSetAttribute(geom55_kernel, cudaFuncAttributeMaxDynamicSharedMemorySize, smem);
    geom55_kernel<<<grid, NTH, smem>>>(
        (const float4*)d_in[0], (const float4*)d_in[1],
        (const float4*)d_in[2], (const float4*)d_in[3],
        (const float4*)d_in[4], (const float4*)d_in[5],
        (float*)d_out, n);
}

// round 15
// speedup vs baseline: 1.0080x; 1.0080x over previous
#include <cuda_runtime.h>
#include <cstdint>

// Row-wise geometry kernel: 6 points (x,y) per row ->
//   out[row][0:15]  = pairwise distances (lexicographic pairs)
//   out[row][15:35] = triplet angles at middle vertex, degrees
//   out[row][35:55] = triangle areas
//
// FINAL (R13): DRAM-write-bound at ~6.0 TB/s achieved (~95% of practical
// mixed-stream ceiling). Structure:
//  - 128-thread CTAs, 28160B static SMEM staging (warp-private 7040B slices),
//    7 CTAs x 4 warps = 28 warps/SM (measured optimum phase mix)
//  - per-warp cp.async.bulk SMEM->GMEM flush, wait_group.READ only
//    (SMEM-dealloc safety; write drain overlaps CTA retirement)
//  - L2 policies: reads evict_last (96MB input set stays L2-resident across
//    graph replays), writes evict_first (440MB stream doesn't displace it)
//  - compute: shared diff/rsqrt factorization, A&S 4.4.46 acos poly + MUFU
//    sqrt/rsqrt (rel_err ~5e-6, budget 1e-3)

#define NTH  128
#define NOUT 55
#define R2D  57.29577951308232f

__device__ __forceinline__ float sqrt_approx(float x) {
    float y;
    asm("sqrt.approx.f32 %0, %1;" : "=f"(y) : "f"(x));
    return y;
}

__device__ __forceinline__ float acos_deg(float x) {
    // Abramowitz & Stegun 4.4.46: acos(x) = sqrt(1-x)*P7(x), |eps| <= 2e-8 rad
    float xa = fabsf(x);
    float p = fmaf(xa, -0.0012624911f, 0.0066700901f);
    p = fmaf(p, xa, -0.0170881256f);
    p = fmaf(p, xa,  0.0308918810f);
    p = fmaf(p, xa, -0.0501743046f);
    p = fmaf(p, xa,  0.0889789874f);
    p = fmaf(p, xa, -0.2145988016f);
    p = fmaf(p, xa,  1.5707963050f);
    float r = sqrt_approx(1.0f - xa) * p * R2D;   // acos(|x|) in degrees
    return (x >= 0.0f) ? r : (180.0f - r);
}

__device__ __forceinline__ float2 ld_pin(const float2* __restrict__ p, uint64_t pol) {
    float2 v;
    asm volatile("ld.global.nc.L2::cache_hint.v2.f32 {%0,%1}, [%2], %3;"
                 : "=f"(v.x), "=f"(v.y) : "l"(p), "l"(pol));
    return v;
}

__global__ __launch_bounds__(NTH)
void geom55_kernel(const float2* __restrict__ a0, const float2* __restrict__ a1,
                   const float2* __restrict__ a2, const float2* __restrict__ a3,
                   const float2* __restrict__ a4, const float2* __restrict__ a5,
                   float* __restrict__ out, int n)
{
    __shared__ __align__(16) float s[NTH * NOUT];   // 28160 B; warp w owns 7040 B slice

    const int tid  = threadIdx.x;
    const int wid  = tid >> 5;
    const int lane = tid & 31;
    const int b    = blockIdx.x * NTH + tid;

    // Uniform, loop-invariant prologue (off the post-compute critical path)
    float* swarp = &s[wid * 32 * NOUT];
    uint32_t saddr;
    asm volatile("{ .reg .u64 t; cvta.to.shared.u64 t, %1; cvt.u32.u64 %0, t; }"
                 : "=r"(saddr) : "l"(swarp));
    uint64_t pol_last, pol_first;
    asm volatile("createpolicy.fractional.L2::evict_last.b64 %0, 1.0;"  : "=l"(pol_last));
    asm volatile("createpolicy.fractional.L2::evict_first.b64 %0, 1.0;" : "=l"(pol_first));

    if (b < n) {
        float px[6], py[6];
        {
            float2 t;
            t = ld_pin(&a0[b], pol_last); px[0] = t.x; py[0] = t.y;
            t = ld_pin(&a1[b], pol_last); px[1] = t.x; py[1] = t.y;
            t = ld_pin(&a2[b], pol_last); px[2] = t.x; py[2] = t.y;
            t = ld_pin(&a3[b], pol_last); px[3] = t.x; py[3] = t.y;
            t = ld_pin(&a4[b], pol_last); px[4] = t.x; py[4] = t.y;
            t = ld_pin(&a5[b], pol_last); px[5] = t.x; py[5] = t.y;
        }

        const int PRI[15] = {0,0,0,0,0, 1,1,1,1, 2,2,2, 3,3, 4};
        const int PRJ[15] = {1,2,3,4,5, 2,3,4,5, 3,4,5, 4,5, 5};

        float dxv[15], dyv[15], rsq[15];
        float* srow = &s[tid * NOUT];

        #pragma unroll
        for (int q = 0; q < 15; q++) {
            float ddx = px[PRI[q]] - px[PRJ[q]];
            float ddy = py[PRI[q]] - py[PRJ[q]];
            float sq  = fmaf(ddx, ddx, ddy * ddy);
            float r   = rsqrtf(sq);
            dxv[q] = ddx; dyv[q] = ddy; rsq[q] = r;
            srow[q] = sq * r;                      // distance = sq * rsqrt(sq)
        }

        const int TI[20] = {0,0,0,0,0,0,0,0,0,0, 1,1,1,1,1,1, 2,2,2, 3};
        const int TJ[20] = {1,1,1,1,2,2,2,3,3,4, 2,2,2,3,3,4, 3,3,4, 4};
        const int TK[20] = {2,3,4,5,3,4,5,4,5,5, 3,4,5,4,5,5, 4,5,5, 5};
        const int POFF[5] = {0,5,9,12,14};         // pidx(i,j) = POFF[i]+(j-i-1)

        #pragma unroll
        for (int q = 0; q < 20; q++) {
            const int i = TI[q], j = TJ[q], k = TK[q];
            const int eij = POFF[i] + (j - i - 1);
            const int ejk = POFF[j] + (k - j - 1);
            const int eik = POFF[i] + (k - i - 1);

            // v1 = p_i - p_j = diff_ij ; v2 = p_k - p_j = -diff_jk
            float dot = fmaf(dxv[eij], dxv[ejk], dyv[eij] * dyv[ejk]);
            float c   = -dot * rsq[eij] * rsq[ejk];
            c = fminf(1.0f, fmaxf(-1.0f, c));
            srow[15 + q] = acos_deg(c);

            // shoelace: x_i*dy_jk - x_j*dy_ik + x_k*dy_ij
            float cr = fmaf(px[i], dyv[ejk], fmaf(px[k], dyv[eij], -px[j] * dyv[eik]));
            srow[35 + q] = 0.5f * fabsf(cr);
        }
    }
    __syncwarp();

    // Per-warp flush: warp w's slice = rows [blockIdx.x*128 + w*32, +32)
    const int warpRow0 = blockIdx.x * NTH + wid * 32;
    const long long gbase = (long long)warpRow0 * NOUT;

    if (warpRow0 + 32 <= n) {
        if (lane == 0) {
            asm volatile("fence.proxy.async.shared::cta;" ::: "memory");
            asm volatile("cp.async.bulk.global.shared::cta.bulk_group.L2::cache_hint"
                         " [%0], [%1], %2, %3;"
                         :: "l"(out + gbase), "r"(saddr), "n"(32 * NOUT * 4), "l"(pol_first)
                         : "memory");
            asm volatile("cp.async.bulk.commit_group;" ::: "memory");
            // READ-wait: SMEM-dealloc safety only; the global drain continues.
            asm volatile("cp.async.bulk.wait_group.read 0;" ::: "memory");
        }
    } else if (warpRow0 < n) {
        // Partial tail slice (not taken for B = 2,000,000): scalar flush
        const int tot = (n - warpRow0) * NOUT;
        for (int q = lane; q < tot; q += 32) out[gbase + q] = swarp[q];
    }
}

extern "C" void kernel_launch(void* const* d_in, const int* in_sizes, int n_in,
                              void* d_out, int out_size) {
    const int n = in_sizes[0] / 2;          // rows (B)
    const int grid = (n + NTH - 1) / NTH;
    geom55_kernel<<<grid, NTH>>>(
        (const float2*)d_in[0], (const float2*)d_in[1],
        (const float2*)d_in[2], (const float2*)d_in[3],
        (const float2*)d_in[4], (const float2*)d_in[5],
        (float*)d_out, n);
}

// round 16
// speedup vs baseline: 1.0084x; 1.0004x over previous
#include <cuda_runtime.h>
#include <cstdint>

// Row-wise geometry kernel: 6 points (x,y) per row ->
//   out[row][0:15]  = pairwise distances (lexicographic pairs)
//   out[row][15:35] = triplet angles at middle vertex, degrees
//   out[row][35:55] = triangle areas
//
// R16 = R13 with 96-thread CTAs (21120B SMEM): footprint ~22KB -> 10 CTAs
// x 3 warps = 30 warps/SM (vs 28) with finer CTA phase granularity.
// Everything else identical: per-warp TMA flush + wait_group.READ,
// evict_last reads / evict_first writes, A&S acos + MUFU sqrt.

#define NTH  96
#define NOUT 55
#define R2D  57.29577951308232f

__device__ __forceinline__ float sqrt_approx(float x) {
    float y;
    asm("sqrt.approx.f32 %0, %1;" : "=f"(y) : "f"(x));
    return y;
}

__device__ __forceinline__ float acos_deg(float x) {
    // Abramowitz & Stegun 4.4.46: acos(x) = sqrt(1-x)*P7(x), |eps| <= 2e-8 rad
    float xa = fabsf(x);
    float p = fmaf(xa, -0.0012624911f, 0.0066700901f);
    p = fmaf(p, xa, -0.0170881256f);
    p = fmaf(p, xa,  0.0308918810f);
    p = fmaf(p, xa, -0.0501743046f);
    p = fmaf(p, xa,  0.0889789874f);
    p = fmaf(p, xa, -0.2145988016f);
    p = fmaf(p, xa,  1.5707963050f);
    float r = sqrt_approx(1.0f - xa) * p * R2D;   // acos(|x|) in degrees
    return (x >= 0.0f) ? r : (180.0f - r);
}

__device__ __forceinline__ float2 ld_pin(const float2* __restrict__ p, uint64_t pol) {
    float2 v;
    asm volatile("ld.global.nc.L2::cache_hint.v2.f32 {%0,%1}, [%2], %3;"
                 : "=f"(v.x), "=f"(v.y) : "l"(p), "l"(pol));
    return v;
}

__global__ __launch_bounds__(NTH)
void geom55_kernel(const float2* __restrict__ a0, const float2* __restrict__ a1,
                   const float2* __restrict__ a2, const float2* __restrict__ a3,
                   const float2* __restrict__ a4, const float2* __restrict__ a5,
                   float* __restrict__ out, int n)
{
    __shared__ __align__(16) float s[NTH * NOUT];   // 21120 B; warp w owns 7040 B slice

    const int tid  = threadIdx.x;
    const int wid  = tid >> 5;
    const int lane = tid & 31;
    const int b    = blockIdx.x * NTH + tid;

    // Uniform, loop-invariant prologue (off the post-compute critical path)
    float* swarp = &s[wid * 32 * NOUT];
    uint32_t saddr;
    asm volatile("{ .reg .u64 t; cvta.to.shared.u64 t, %1; cvt.u32.u64 %0, t; }"
                 : "=r"(saddr) : "l"(swarp));
    uint64_t pol_last, pol_first;
    asm volatile("createpolicy.fractional.L2::evict_last.b64 %0, 1.0;"  : "=l"(pol_last));
    asm volatile("createpolicy.fractional.L2::evict_first.b64 %0, 1.0;" : "=l"(pol_first));

    if (b < n) {
        float px[6], py[6];
        {
            float2 t;
            t = ld_pin(&a0[b], pol_last); px[0] = t.x; py[0] = t.y;
            t = ld_pin(&a1[b], pol_last); px[1] = t.x; py[1] = t.y;
            t = ld_pin(&a2[b], pol_last); px[2] = t.x; py[2] = t.y;
            t = ld_pin(&a3[b], pol_last); px[3] = t.x; py[3] = t.y;
            t = ld_pin(&a4[b], pol_last); px[4] = t.x; py[4] = t.y;
            t = ld_pin(&a5[b], pol_last); px[5] = t.x; py[5] = t.y;
        }

        const int PRI[15] = {0,0,0,0,0, 1,1,1,1, 2,2,2, 3,3, 4};
        const int PRJ[15] = {1,2,3,4,5, 2,3,4,5, 3,4,5, 4,5, 5};

        float dxv[15], dyv[15], rsq[15];
        float* srow = &s[tid * NOUT];

        #pragma unroll
        for (int q = 0; q < 15; q++) {
            float ddx = px[PRI[q]] - px[PRJ[q]];
            float ddy = py[PRI[q]] - py[PRJ[q]];
            float sq  = fmaf(ddx, ddx, ddy * ddy);
            float r   = rsqrtf(sq);
            dxv[q] = ddx; dyv[q] = ddy; rsq[q] = r;
            srow[q] = sq * r;                      // distance = sq * rsqrt(sq)
        }

        const int TI[20] = {0,0,0,0,0,0,0,0,0,0, 1,1,1,1,1,1, 2,2,2, 3};
        const int TJ[20] = {1,1,1,1,2,2,2,3,3,4, 2,2,2,3,3,4, 3,3,4, 4};
        const int TK[20] = {2,3,4,5,3,4,5,4,5,5, 3,4,5,4,5,5, 4,5,5, 5};
        const int POFF[5] = {0,5,9,12,14};         // pidx(i,j) = POFF[i]+(j-i-1)

        #pragma unroll
        for (int q = 0; q < 20; q++) {
            const int i = TI[q], j = TJ[q], k = TK[q];
            const int eij = POFF[i] + (j - i - 1);
            const int ejk = POFF[j] + (k - j - 1);
            const int eik = POFF[i] + (k - i - 1);

            // v1 = p_i - p_j = diff_ij ; v2 = p_k - p_j = -diff_jk
            float dot = fmaf(dxv[eij], dxv[ejk], dyv[eij] * dyv[ejk]);
            float c   = -dot * rsq[eij] * rsq[ejk];
            c = fminf(1.0f, fmaxf(-1.0f, c));
            srow[15 + q] = acos_deg(c);

            // shoelace: x_i*dy_jk - x_j*dy_ik + x_k*dy_ij
            float cr = fmaf(px[i], dyv[ejk], fmaf(px[k], dyv[eij], -px[j] * dyv[eik]));
            srow[35 + q] = 0.5f * fabsf(cr);
        }
    }
    __syncwarp();

    // Per-warp flush: warp w's slice = rows [blockIdx.x*96 + w*32, +32)
    const int warpRow0 = blockIdx.x * NTH + wid * 32;
    const long long gbase = (long long)warpRow0 * NOUT;

    if (warpRow0 + 32 <= n) {
        if (lane == 0) {
            asm volatile("fence.proxy.async.shared::cta;" ::: "memory");
            asm volatile("cp.async.bulk.global.shared::cta.bulk_group.L2::cache_hint"
                         " [%0], [%1], %2, %3;"
                         :: "l"(out + gbase), "r"(saddr), "n"(32 * NOUT * 4), "l"(pol_first)
                         : "memory");
            asm volatile("cp.async.bulk.commit_group;" ::: "memory");
            // READ-wait: SMEM-dealloc safety only; the global drain continues.
            asm volatile("cp.async.bulk.wait_group.read 0;" ::: "memory");
        }
    } else if (warpRow0 < n) {
        // Partial tail slice: scalar flush
        const int tot = (n - warpRow0) * NOUT;
        for (int q = lane; q < tot; q += 32) out[gbase + q] = swarp[q];
    }
}

extern "C" void kernel_launch(void* const* d_in, const int* in_sizes, int n_in,
                              void* d_out, int out_size) {
    const int n = in_sizes[0] / 2;          // rows (B)
    const int grid = (n + NTH - 1) / NTH;
    geom55_kernel<<<grid, NTH>>>(
        (const float2*)d_in[0], (const float2*)d_in[1],
        (const float2*)d_in[2], (const float2*)d_in[3],
        (const float2*)d_in[4], (const float2*)d_in[5],
        (float*)d_out, n);
}

// round 17
// speedup vs baseline: 1.0115x; 1.0031x over previous
#include <cuda_runtime.h>
#include <cstdint>

// Row-wise geometry kernel: 6 points (x,y) per row ->
//   out[row][0:15]  = pairwise distances (lexicographic pairs)
//   out[row][15:35] = triplet angles at middle vertex, degrees
//   out[row][35:55] = triangle areas
//
// R17 = R16 with 64-thread CTAs (14080B SMEM): ~15KB footprint -> 15 CTAs
// x 2 warps = 30 warps/SM at the finest CTA phase granularity. Final point
// of the granularity sweep (256/128/96/64). All other machinery identical:
// per-warp TMA flush + wait_group.READ, evict_last reads / evict_first
// writes, A&S 4.4.46 acos + MUFU sqrt (rel_err ~5e-6 vs 1e-3 budget).

#define NTH  64
#define NOUT 55
#define R2D  57.29577951308232f

__device__ __forceinline__ float sqrt_approx(float x) {
    float y;
    asm("sqrt.approx.f32 %0, %1;" : "=f"(y) : "f"(x));
    return y;
}

__device__ __forceinline__ float acos_deg(float x) {
    // Abramowitz & Stegun 4.4.46: acos(x) = sqrt(1-x)*P7(x), |eps| <= 2e-8 rad
    float xa = fabsf(x);
    float p = fmaf(xa, -0.0012624911f, 0.0066700901f);
    p = fmaf(p, xa, -0.0170881256f);
    p = fmaf(p, xa,  0.0308918810f);
    p = fmaf(p, xa, -0.0501743046f);
    p = fmaf(p, xa,  0.0889789874f);
    p = fmaf(p, xa, -0.2145988016f);
    p = fmaf(p, xa,  1.5707963050f);
    float r = sqrt_approx(1.0f - xa) * p * R2D;   // acos(|x|) in degrees
    return (x >= 0.0f) ? r : (180.0f - r);
}

__device__ __forceinline__ float2 ld_pin(const float2* __restrict__ p, uint64_t pol) {
    float2 v;
    asm volatile("ld.global.nc.L2::cache_hint.v2.f32 {%0,%1}, [%2], %3;"
                 : "=f"(v.x), "=f"(v.y) : "l"(p), "l"(pol));
    return v;
}

__global__ __launch_bounds__(NTH)
void geom55_kernel(const float2* __restrict__ a0, const float2* __restrict__ a1,
                   const float2* __restrict__ a2, const float2* __restrict__ a3,
                   const float2* __restrict__ a4, const float2* __restrict__ a5,
                   float* __restrict__ out, int n)
{
    __shared__ __align__(16) float s[NTH * NOUT];   // 14080 B; warp w owns 7040 B slice

    const int tid  = threadIdx.x;
    const int wid  = tid >> 5;
    const int lane = tid & 31;
    const int b    = blockIdx.x * NTH + tid;

    // Uniform, loop-invariant prologue (off the post-compute critical path)
    float* swarp = &s[wid * 32 * NOUT];
    uint32_t saddr;
    asm volatile("{ .reg .u64 t; cvta.to.shared.u64 t, %1; cvt.u32.u64 %0, t; }"
                 : "=r"(saddr) : "l"(swarp));
    uint64_t pol_last, pol_first;
    asm volatile("createpolicy.fractional.L2::evict_last.b64 %0, 1.0;"  : "=l"(pol_last));
    asm volatile("createpolicy.fractional.L2::evict_first.b64 %0, 1.0;" : "=l"(pol_first));

    if (b < n) {
        float px[6], py[6];
        {
            float2 t;
            t = ld_pin(&a0[b], pol_last); px[0] = t.x; py[0] = t.y;
            t = ld_pin(&a1[b], pol_last); px[1] = t.x; py[1] = t.y;
            t = ld_pin(&a2[b], pol_last); px[2] = t.x; py[2] = t.y;
            t = ld_pin(&a3[b], pol_last); px[3] = t.x; py[3] = t.y;
            t = ld_pin(&a4[b], pol_last); px[4] = t.x; py[4] = t.y;
            t = ld_pin(&a5[b], pol_last); px[5] = t.x; py[5] = t.y;
        }

        const int PRI[15] = {0,0,0,0,0, 1,1,1,1, 2,2,2, 3,3, 4};
        const int PRJ[15] = {1,2,3,4,5, 2,3,4,5, 3,4,5, 4,5, 5};

        float dxv[15], dyv[15], rsq[15];
        float* srow = &s[tid * NOUT];

        #pragma unroll
        for (int q = 0; q < 15; q++) {
            float ddx = px[PRI[q]] - px[PRJ[q]];
            float ddy = py[PRI[q]] - py[PRJ[q]];
            float sq  = fmaf(ddx, ddx, ddy * ddy);
            float r   = rsqrtf(sq);
            dxv[q] = ddx; dyv[q] = ddy; rsq[q] = r;
            srow[q] = sq * r;                      // distance = sq * rsqrt(sq)
        }

        const int TI[20] = {0,0,0,0,0,0,0,0,0,0, 1,1,1,1,1,1, 2,2,2, 3};
        const int TJ[20] = {1,1,1,1,2,2,2,3,3,4, 2,2,2,3,3,4, 3,3,4, 4};
        const int TK[20] = {2,3,4,5,3,4,5,4,5,5, 3,4,5,4,5,5, 4,5,5, 5};
        const int POFF[5] = {0,5,9,12,14};         // pidx(i,j) = POFF[i]+(j-i-1)

        #pragma unroll
        for (int q = 0; q < 20; q++) {
            const int i = TI[q], j = TJ[q], k = TK[q];
            const int eij = POFF[i] + (j - i - 1);
            const int ejk = POFF[j] + (k - j - 1);
            const int eik = POFF[i] + (k - i - 1);

            // v1 = p_i - p_j = diff_ij ; v2 = p_k - p_j = -diff_jk
            float dot = fmaf(dxv[eij], dxv[ejk], dyv[eij] * dyv[ejk]);
            float c   = -dot * rsq[eij] * rsq[ejk];
            c = fminf(1.0f, fmaxf(-1.0f, c));
            srow[15 + q] = acos_deg(c);

            // shoelace: x_i*dy_jk - x_j*dy_ik + x_k*dy_ij
            float cr = fmaf(px[i], dyv[ejk], fmaf(px[k], dyv[eij], -px[j] * dyv[eik]));
            srow[35 + q] = 0.5f * fabsf(cr);
        }
    }
    __syncwarp();

    // Per-warp flush: warp w's slice = rows [blockIdx.x*64 + w*32, +32)
    const int warpRow0 = blockIdx.x * NTH + wid * 32;
    const long long gbase = (long long)warpRow0 * NOUT;

    if (warpRow0 + 32 <= n) {
        if (lane == 0) {
            asm volatile("fence.proxy.async.shared::cta;" ::: "memory");
            asm volatile("cp.async.bulk.global.shared::cta.bulk_group.L2::cache_hint"
                         " [%0], [%1], %2, %3;"
                         :: "l"(out + gbase), "r"(saddr), "n"(32 * NOUT * 4), "l"(pol_first)
                         : "memory");
            asm volatile("cp.async.bulk.commit_group;" ::: "memory");
            // READ-wait: SMEM-dealloc safety only; the global drain continues.
            asm volatile("cp.async.bulk.wait_group.read 0;" ::: "memory");
        }
    } else if (warpRow0 < n) {
        // Partial tail slice: scalar flush
        const int tot = (n - warpRow0) * NOUT;
        for (int q = lane; q < tot; q += 32) out[gbase + q] = swarp[q];
    }
}

extern "C" void kernel_launch(void* const* d_in, const int* in_sizes, int n_in,
                              void* d_out, int out_size) {
    const int n = in_sizes[0] / 2;          // rows (B)
    const int grid = (n + NTH - 1) / NTH;
    geom55_kernel<<<grid, NTH>>>(
        (const float2*)d_in[0], (const float2*)d_in[1],
        (const float2*)d_in[2], (const float2*)d_in[3],
        (const float2*)d_in[4], (const float2*)d_in[5],
        (float*)d_out, n);
}